// round 7
// baseline (speedup 1.0000x reference)
#include <cuda_runtime.h>
#include <cuda_bf16.h>
#include <cstdint>

#define NU 200000
#define NI 200000
#define D  64
#define MAXE 2000000
#define NB_I ((NI + 255) / 256)
#define NB_U ((NU + 255) / 256)

// ---------------------------------------------------------------------------
// Device scratch (no cudaMalloc allowed)
// ---------------------------------------------------------------------------
__device__ float g_h_i[(size_t)NI * D];
__device__ float g_h_u[(size_t)NU * D];
__device__ int g_deg_i[NI];
__device__ int g_deg_u[NU];
__device__ int g_rp_i[NI + 1];
__device__ int g_rp_u[NU + 1];
__device__ int g_cur_i[NI];
__device__ int g_cur_u[NU];
__device__ int g_perm_ui[MAXE];
__device__ int g_perm_iu[MAXE];
__device__ int g_bsum[1024];
__device__ int g_boff[1024];

__device__ __forceinline__ uint32_t smem_to_u32(const void* p) {
    uint32_t a;
    asm("{ .reg .u64 t; cvta.to.shared.u64 t, %1; cvt.u32.u64 %0, t; }"
        : "=r"(a) : "l"(p));
    return a;
}

// ---------------------------------------------------------------------------
// CSR build
// ---------------------------------------------------------------------------
__global__ void hist_k(const int* __restrict__ dst, int E, int* __restrict__ deg)
{
    int i = blockIdx.x * blockDim.x + threadIdx.x;
    if (i < E) atomicAdd(&deg[__ldg(dst + i)], 1);
}

__global__ void scanA_k(const int* __restrict__ deg, int N, int* __restrict__ bsum)
{
    __shared__ int s[256];
    int tid = threadIdx.x;
    int i = blockIdx.x * 256 + tid;
    s[tid] = (i < N) ? deg[i] : 0;
    __syncthreads();
    #pragma unroll
    for (int o = 128; o; o >>= 1) {
        if (tid < o) s[tid] += s[tid + o];
        __syncthreads();
    }
    if (tid == 0) bsum[blockIdx.x] = s[0];
}

__global__ void scanB_k(const int* __restrict__ bsum, int NB,
                        int* __restrict__ boff, int* __restrict__ rowptr, int N)
{
    __shared__ int s[1024];
    int tid = threadIdx.x;
    int v = (tid < NB) ? bsum[tid] : 0;
    s[tid] = v;
    __syncthreads();
    for (int o = 1; o < 1024; o <<= 1) {
        int t = (tid >= o) ? s[tid - o] : 0;
        __syncthreads();
        s[tid] += t;
        __syncthreads();
    }
    if (tid < NB) boff[tid] = s[tid] - v;
    if (tid == NB - 1) rowptr[N] = s[tid];
}

__global__ void scanC_k(const int* __restrict__ deg, int N,
                        const int* __restrict__ boff,
                        int* __restrict__ rowptr, int* __restrict__ cursor)
{
    __shared__ int s[256];
    int tid = threadIdx.x;
    int i = blockIdx.x * 256 + tid;
    int v = (i < N) ? deg[i] : 0;
    s[tid] = v;
    __syncthreads();
    #pragma unroll
    for (int o = 1; o < 256; o <<= 1) {
        int t = (tid >= o) ? s[tid - o] : 0;
        __syncthreads();
        s[tid] += t;
        __syncthreads();
    }
    if (i < N) {
        int ex = boff[blockIdx.x] + s[tid] - v;
        rowptr[i] = ex;
        cursor[i] = ex;
    }
}

__global__ void permute_k(const int* __restrict__ edge, int E,
                          int* __restrict__ cursor, int* __restrict__ perm)
{
    int i = blockIdx.x * blockDim.x + threadIdx.x;
    if (i < E) {
        int s = __ldg(edge + i);
        int d = __ldg(edge + E + i);
        int slot = atomicAdd(&cursor[d], 1);
        perm[slot] = s;
    }
}

// ---------------------------------------------------------------------------
// Fused SAGE layer: gather-mean aggregation straight into shared bf16-split
// A tile, then tensor-core GEMM (mma.sync m16n8k16 bf16, 3-pass fp32
// emulation: A_hi*B_hi + A_lo*B_hi + A_hi*B_lo), bias, row L2-norm, relu.
// Block = 256 threads, 128 rows. Warp w aggregates rows w*16..w*16+15.
// SMEM (PKB=272B pitch): A_hi[128], A_lo[128], B_hi[64], B_lo[64], bias.
// ---------------------------------------------------------------------------
#define PKB 272
#define SM_AHI  0
#define SM_ALO  (128 * PKB)
#define SM_BHI  (2 * 128 * PKB)
#define SM_BLO  (SM_BHI + 64 * PKB)
#define SM_BIAS (SM_BHI + 2 * 64 * PKB)
#define POST_SMEM (SM_BIAS + 256)

#define LDMATRIX_X4(r0, r1, r2, r3, addr) \
    asm volatile("ldmatrix.sync.aligned.m8n8.x4.shared.b16 {%0, %1, %2, %3}, [%4];" \
                 : "=r"(r0), "=r"(r1), "=r"(r2), "=r"(r3) : "r"(addr))

#define MMA_BF16(d, a0, a1, a2, a3, b0, b1) \
    asm volatile("mma.sync.aligned.m16n8k16.row.col.f32.bf16.bf16.f32 " \
                 "{%0, %1, %2, %3}, {%4, %5, %6, %7}, {%8, %9}, {%0, %1, %2, %3};" \
                 : "+f"((d)[0]), "+f"((d)[1]), "+f"((d)[2]), "+f"((d)[3]) \
                 : "r"(a0), "r"(a1), "r"(a2), "r"(a3), "r"(b0), "r"(b1))

__device__ __forceinline__ uint32_t bf2u(__nv_bfloat162 v) {
    return *reinterpret_cast<uint32_t*>(&v);
}

// convert float2 -> (hi bf16x2, lo bf16x2)
__device__ __forceinline__ void split2(float x, float y, uint32_t& hi, uint32_t& lo) {
    __nv_bfloat162 h = __float22bfloat162_rn(make_float2(x, y));
    float2 hf = __bfloat1622float2(h);
    __nv_bfloat162 l = __float22bfloat162_rn(make_float2(x - hf.x, y - hf.y));
    hi = bf2u(h);
    lo = bf2u(l);
}

__global__ void __launch_bounds__(256)
sage_fused_tc(const float* __restrict__ src,      // gather source rows
              const int*   __restrict__ remapS,   // src remap (or null)
              const int*   __restrict__ rowptr,
              const int*   __restrict__ perm,
              const float* __restrict__ xdst_base,
              const int*   __restrict__ remapX,   // dst remap (or null)
              const float* __restrict__ Wl,
              const float* __restrict__ bl,
              const float* __restrict__ Wr,
              float* __restrict__ out,
              int N, int relu)
{
    extern __shared__ char smem[];
    uint32_t sb = smem_to_u32(smem);
    const int tid = threadIdx.x;
    const int warp = tid >> 5;
    const int lane = tid & 31;
    const int r0 = blockIdx.x * 128;

    // ---- Stage B = W^T hi/lo (all threads) ----
    #pragma unroll
    for (int pp = 0; pp < 8; pp++) {
        int i = tid + pp * 256;             // f4 idx 0..2047 over [128 k][16 c-groups]
        int k = i >> 4;
        int c = (i & 15) << 2;
        float4 w = (k < 64)
            ? *reinterpret_cast<const float4*>(Wl + k * D + c)
            : *reinterpret_cast<const float4*>(Wr + (k - 64) * D + c);
        float wv[4] = { w.x, w.y, w.z, w.w };
        #pragma unroll
        for (int j = 0; j < 4; j++) {
            __nv_bfloat16 hi = __float2bfloat16(wv[j]);
            __nv_bfloat16 lo = __float2bfloat16(wv[j] - __bfloat162float(hi));
            int n = c + j;
            *reinterpret_cast<__nv_bfloat16*>(smem + SM_BHI + n * PKB + k * 2) = hi;
            *reinterpret_cast<__nv_bfloat16*>(smem + SM_BLO + n * PKB + k * 2) = lo;
        }
    }
    if (tid < 64) *reinterpret_cast<float*>(smem + SM_BIAS + tid * 4) = bl[tid];

    // ---- Phase 1: gather-mean into A tile (warp w -> rows w*16..w*16+15) ----
    for (int rr = 0; rr < 16; rr++) {
        int row = warp * 16 + rr;
        int gr = r0 + row;
        char* aHiRow = smem + SM_AHI + row * PKB;
        char* aLoRow = smem + SM_ALO + row * PKB;

        if (gr < N) {
            int start = __ldg(rowptr + gr);
            int end   = __ldg(rowptr + gr + 1);
            float ax = 0.0f, ay = 0.0f;
            for (int base = start; base < end; base += 32) {
                int rem = end - base;
                int idx = 0;
                if (lane < rem) {
                    idx = __ldg(perm + base + lane);
                    if (remapS) idx = __ldg(remapS + idx);
                }
                int m = rem < 32 ? rem : 32;
                for (int j = 0; j < m; j++) {
                    int s2 = __shfl_sync(0xffffffffu, idx, j);
                    float2 v = *reinterpret_cast<const float2*>(
                        src + (size_t)s2 * D + lane * 2);
                    ax += v.x;
                    ay += v.y;
                }
            }
            int deg = end - start;
            float inv = (deg > 0) ? (1.0f / (float)deg) : 0.0f;
            uint32_t hi, lo;
            split2(ax * inv, ay * inv, hi, lo);
            *reinterpret_cast<uint32_t*>(aHiRow + lane * 4) = hi;
            *reinterpret_cast<uint32_t*>(aLoRow + lane * 4) = lo;

            // x row -> k 64..127
            int xr = remapX ? __ldg(remapX + gr) : gr;
            float2 xv = *reinterpret_cast<const float2*>(
                xdst_base + (size_t)xr * D + lane * 2);
            split2(xv.x, xv.y, hi, lo);
            *reinterpret_cast<uint32_t*>(aHiRow + 128 + lane * 4) = hi;
            *reinterpret_cast<uint32_t*>(aLoRow + 128 + lane * 4) = lo;
        } else {
            *reinterpret_cast<uint32_t*>(aHiRow + lane * 4) = 0u;
            *reinterpret_cast<uint32_t*>(aLoRow + lane * 4) = 0u;
            *reinterpret_cast<uint32_t*>(aHiRow + 128 + lane * 4) = 0u;
            *reinterpret_cast<uint32_t*>(aLoRow + 128 + lane * 4) = 0u;
        }
    }
    __syncthreads();

    // ---- Phase 2: MMA mainloop (3 passes x 8 k-steps, 8 n-tiles) ----
    float d[8][4];
    #pragma unroll
    for (int t = 0; t < 8; t++) {
        d[t][0] = 0.f; d[t][1] = 0.f; d[t][2] = 0.f; d[t][3] = 0.f;
    }

    const uint32_t aRowOff = (uint32_t)(warp * 16 + (lane & 15)) * PKB
                           + (uint32_t)(lane >> 4) * 16;
    const uint32_t bRowOff = (uint32_t)(lane >> 2) * PKB + (uint32_t)(lane & 3) * 4;

    #pragma unroll
    for (int pass = 0; pass < 3; pass++) {
        uint32_t aBase = sb + (pass == 1 ? SM_ALO : SM_AHI) + aRowOff;
        uint32_t bOff  = (pass == 2 ? SM_BLO : SM_BHI) + bRowOff;
        #pragma unroll
        for (int ks = 0; ks < 8; ks++) {
            uint32_t a0, a1, a2, a3;
            LDMATRIX_X4(a0, a1, a2, a3, aBase + ks * 32);
            #pragma unroll
            for (int t = 0; t < 8; t++) {
                uint32_t b0 = *reinterpret_cast<const uint32_t*>(
                    (const char*)smem + bOff + t * 8 * PKB + ks * 32);
                uint32_t b1 = *reinterpret_cast<const uint32_t*>(
                    (const char*)smem + bOff + t * 8 * PKB + ks * 32 + 16);
                MMA_BF16(d[t], a0, a1, a2, a3, b0, b1);
            }
        }
    }

    // ---- Epilogue: bias, row L2 norm (4-lane groups), relu, store ----
    const float* bias = reinterpret_cast<const float*>(smem + SM_BIAS);
    int cBase = (lane & 3) * 2;
    float ssl = 0.f, ssh = 0.f;
    #pragma unroll
    for (int t = 0; t < 8; t++) {
        int c = t * 8 + cBase;
        float b0 = bias[c], b1 = bias[c + 1];
        d[t][0] += b0; d[t][1] += b1;
        d[t][2] += b0; d[t][3] += b1;
        ssl = fmaf(d[t][0], d[t][0], ssl); ssl = fmaf(d[t][1], d[t][1], ssl);
        ssh = fmaf(d[t][2], d[t][2], ssh); ssh = fmaf(d[t][3], d[t][3], ssh);
    }
    ssl += __shfl_xor_sync(0xffffffffu, ssl, 1);
    ssl += __shfl_xor_sync(0xffffffffu, ssl, 2);
    ssh += __shfl_xor_sync(0xffffffffu, ssh, 1);
    ssh += __shfl_xor_sync(0xffffffffu, ssh, 2);

    int rlo = r0 + warp * 16 + (lane >> 2);
    int rhi = rlo + 8;
    float invl = 1.0f / fmaxf(sqrtf(ssl), 1e-12f);
    float invh = 1.0f / fmaxf(sqrtf(ssh), 1e-12f);

    if (rlo < N) {
        float* op = out + (size_t)rlo * D + cBase;
        #pragma unroll
        for (int t = 0; t < 8; t++) {
            float2 v = make_float2(d[t][0] * invl, d[t][1] * invl);
            if (relu) { v.x = fmaxf(v.x, 0.f); v.y = fmaxf(v.y, 0.f); }
            *reinterpret_cast<float2*>(op + t * 8) = v;
        }
    }
    if (rhi < N) {
        float* op = out + (size_t)rhi * D + cBase;
        #pragma unroll
        for (int t = 0; t < 8; t++) {
            float2 v = make_float2(d[t][2] * invh, d[t][3] * invh);
            if (relu) { v.x = fmaxf(v.x, 0.f); v.y = fmaxf(v.y, 0.f); }
            *reinterpret_cast<float2*>(op + t * 8) = v;
        }
    }
}

// ---------------------------------------------------------------------------
// Launch
// ---------------------------------------------------------------------------
extern "C" void kernel_launch(void* const* d_in, const int* in_sizes, int n_in,
                              void* d_out, int out_size)
{
    const float* emb_user = (const float*)d_in[0];
    const float* emb_item = (const float*)d_in[1];
    const float* W1l_ui = (const float*)d_in[2];
    const float* b1_ui  = (const float*)d_in[3];
    const float* W1r_ui = (const float*)d_in[4];
    const float* W1l_iu = (const float*)d_in[5];
    const float* b1_iu  = (const float*)d_in[6];
    const float* W1r_iu = (const float*)d_in[7];
    const float* W2l_ui = (const float*)d_in[8];
    const float* b2_ui  = (const float*)d_in[9];
    const float* W2r_ui = (const float*)d_in[10];
    const float* W2l_iu = (const float*)d_in[11];
    const float* b2_iu  = (const float*)d_in[12];
    const float* W2r_iu = (const float*)d_in[13];
    const int* n_id_user = (const int*)d_in[14];
    const int* n_id_item = (const int*)d_in[15];
    const int* edge_ui   = (const int*)d_in[16];
    const int* edge_iu   = (const int*)d_in[17];

    const int E_ui = in_sizes[16] / 2;
    const int E_iu = in_sizes[17] / 2;

    float* out = (float*)d_out;
    float* out_user = out;
    float* out_item = out + (size_t)NU * D;

    float *h_i, *h_u;
    int *deg_i, *deg_u, *rp_i, *rp_u, *cur_i, *cur_u, *perm_ui, *perm_iu, *bsum, *boff;
    cudaGetSymbolAddress((void**)&h_i, g_h_i);
    cudaGetSymbolAddress((void**)&h_u, g_h_u);
    cudaGetSymbolAddress((void**)&deg_i, g_deg_i);
    cudaGetSymbolAddress((void**)&deg_u, g_deg_u);
    cudaGetSymbolAddress((void**)&rp_i, g_rp_i);
    cudaGetSymbolAddress((void**)&rp_u, g_rp_u);
    cudaGetSymbolAddress((void**)&cur_i, g_cur_i);
    cudaGetSymbolAddress((void**)&cur_u, g_cur_u);
    cudaGetSymbolAddress((void**)&perm_ui, g_perm_ui);
    cudaGetSymbolAddress((void**)&perm_iu, g_perm_iu);
    cudaGetSymbolAddress((void**)&bsum, g_bsum);
    cudaGetSymbolAddress((void**)&boff, g_boff);

    const int TPB = 256;
    const int eBlocksUI = (E_ui + TPB - 1) / TPB;
    const int eBlocksIU = (E_iu + TPB - 1) / TPB;
    const int fusedBlocksI = (NI + 127) / 128;
    const int fusedBlocksU = (NU + 127) / 128;

    cudaFuncSetAttribute(sage_fused_tc,
                         cudaFuncAttributeMaxDynamicSharedMemorySize, POST_SMEM);

    // ---- CSR build ----
    cudaMemsetAsync(deg_i, 0, NI * sizeof(int));
    cudaMemsetAsync(deg_u, 0, NU * sizeof(int));

    hist_k<<<eBlocksUI, TPB>>>(edge_ui + E_ui, E_ui, deg_i);
    hist_k<<<eBlocksIU, TPB>>>(edge_iu + E_iu, E_iu, deg_u);

    scanA_k<<<NB_I, 256>>>(deg_i, NI, bsum);
    scanB_k<<<1, 1024>>>(bsum, NB_I, boff, rp_i, NI);
    scanC_k<<<NB_I, 256>>>(deg_i, NI, boff, rp_i, cur_i);
    permute_k<<<eBlocksUI, TPB>>>(edge_ui, E_ui, cur_i, perm_ui);

    scanA_k<<<NB_U, 256>>>(deg_u, NU, bsum);
    scanB_k<<<1, 1024>>>(bsum, NB_U, boff, rp_u, NU);
    scanC_k<<<NB_U, 256>>>(deg_u, NU, boff, rp_u, cur_u);
    permute_k<<<eBlocksIU, TPB>>>(edge_iu, E_iu, cur_u, perm_iu);

    // ---- Layer 1 (fused agg + GEMM + norm + relu) ----
    sage_fused_tc<<<fusedBlocksI, TPB, POST_SMEM>>>(
        emb_user, n_id_user, rp_i, perm_ui,
        emb_item, n_id_item, W1l_ui, b1_ui, W1r_ui, h_i, NI, 1);
    sage_fused_tc<<<fusedBlocksU, TPB, POST_SMEM>>>(
        emb_item, n_id_item, rp_u, perm_iu,
        emb_user, n_id_user, W1l_iu, b1_iu, W1r_iu, h_u, NU, 1);

    // ---- Layer 2 (same CSR, no remaps) ----
    sage_fused_tc<<<fusedBlocksI, TPB, POST_SMEM>>>(
        h_u, nullptr, rp_i, perm_ui,
        h_i, nullptr, W2l_ui, b2_ui, W2r_ui, out_item, NI, 0);
    sage_fused_tc<<<fusedBlocksU, TPB, POST_SMEM>>>(
        h_i, nullptr, rp_u, perm_iu,
        h_u, nullptr, W2l_iu, b2_iu, W2r_iu, out_user, NU, 0);
}

// round 8
// speedup vs baseline: 1.9409x; 1.9409x over previous
#include <cuda_runtime.h>
#include <cuda_bf16.h>
#include <cstdint>

#define NU 200000
#define NI 200000
#define D  64
#define MAXE 2000000
#define NB_I ((NI + 255) / 256)
#define NB_U ((NU + 255) / 256)

// ---------------------------------------------------------------------------
// Device scratch (no cudaMalloc allowed)
// ---------------------------------------------------------------------------
__device__ float g_acc_i[(size_t)NI * D];
__device__ float g_acc_u[(size_t)NU * D];
__device__ float g_h_i[(size_t)NI * D];
__device__ float g_h_u[(size_t)NU * D];
__device__ int g_deg_i[NI];
__device__ int g_deg_u[NU];
__device__ int g_rp_i[NI + 1];
__device__ int g_rp_u[NU + 1];
__device__ int g_cur_i[NI];
__device__ int g_cur_u[NU];
__device__ int g_perm_ui[MAXE];
__device__ int g_perm_iu[MAXE];
__device__ int g_bsum[1024];
__device__ int g_boff[1024];
// Prepacked weights: 4 sets x [64 n][128 k] bf16, hi and lo planes
__device__ __nv_bfloat16 g_Bhi[4][64 * 128];
__device__ __nv_bfloat16 g_Blo[4][64 * 128];

__device__ __forceinline__ uint32_t smem_to_u32(const void* p) {
    uint32_t a;
    asm("{ .reg .u64 t; cvta.to.shared.u64 t, %1; cvt.u32.u64 %0, t; }"
        : "=r"(a) : "l"(p));
    return a;
}

// ---------------------------------------------------------------------------
// Weight prepack: B[set][n][k] = (k<64 ? Wl[k][n] : Wr[k-64][n]) split hi/lo
// ---------------------------------------------------------------------------
__global__ void prepack_w_k(const float* __restrict__ W1l_ui, const float* __restrict__ W1r_ui,
                            const float* __restrict__ W1l_iu, const float* __restrict__ W1r_iu,
                            const float* __restrict__ W2l_ui, const float* __restrict__ W2r_ui,
                            const float* __restrict__ W2l_iu, const float* __restrict__ W2r_iu)
{
    int i = blockIdx.x * blockDim.x + threadIdx.x;  // 4*64*128 = 32768 threads
    if (i >= 4 * 64 * 128) return;
    int set = i >> 13;
    int n = (i >> 7) & 63;
    int k = i & 127;
    const float* Wl; const float* Wr;
    switch (set) {
        case 0: Wl = W1l_ui; Wr = W1r_ui; break;
        case 1: Wl = W1l_iu; Wr = W1r_iu; break;
        case 2: Wl = W2l_ui; Wr = W2r_ui; break;
        default: Wl = W2l_iu; Wr = W2r_iu; break;
    }
    float w = (k < 64) ? Wl[k * D + n] : Wr[(k - 64) * D + n];
    __nv_bfloat16 hi = __float2bfloat16(w);
    __nv_bfloat16 lo = __float2bfloat16(w - __bfloat162float(hi));
    g_Bhi[set][n * 128 + k] = hi;
    g_Blo[set][n * 128 + k] = lo;
}

// ---------------------------------------------------------------------------
// CSR build
// ---------------------------------------------------------------------------
__global__ void hist_k(const int* __restrict__ dst, int E, int* __restrict__ deg)
{
    int i = blockIdx.x * blockDim.x + threadIdx.x;
    if (i < E) atomicAdd(&deg[__ldg(dst + i)], 1);
}

__global__ void scanA_k(const int* __restrict__ deg, int N, int* __restrict__ bsum)
{
    __shared__ int s[256];
    int tid = threadIdx.x;
    int i = blockIdx.x * 256 + tid;
    s[tid] = (i < N) ? deg[i] : 0;
    __syncthreads();
    #pragma unroll
    for (int o = 128; o; o >>= 1) {
        if (tid < o) s[tid] += s[tid + o];
        __syncthreads();
    }
    if (tid == 0) bsum[blockIdx.x] = s[0];
}

__global__ void scanB_k(const int* __restrict__ bsum, int NB,
                        int* __restrict__ boff, int* __restrict__ rowptr, int N)
{
    __shared__ int s[1024];
    int tid = threadIdx.x;
    int v = (tid < NB) ? bsum[tid] : 0;
    s[tid] = v;
    __syncthreads();
    for (int o = 1; o < 1024; o <<= 1) {
        int t = (tid >= o) ? s[tid - o] : 0;
        __syncthreads();
        s[tid] += t;
        __syncthreads();
    }
    if (tid < NB) boff[tid] = s[tid] - v;
    if (tid == NB - 1) rowptr[N] = s[tid];
}

__global__ void scanC_k(const int* __restrict__ deg, int N,
                        const int* __restrict__ boff,
                        int* __restrict__ rowptr, int* __restrict__ cursor)
{
    __shared__ int s[256];
    int tid = threadIdx.x;
    int i = blockIdx.x * 256 + tid;
    int v = (i < N) ? deg[i] : 0;
    s[tid] = v;
    __syncthreads();
    #pragma unroll
    for (int o = 1; o < 256; o <<= 1) {
        int t = (tid >= o) ? s[tid - o] : 0;
        __syncthreads();
        s[tid] += t;
        __syncthreads();
    }
    if (i < N) {
        int ex = boff[blockIdx.x] + s[tid] - v;
        rowptr[i] = ex;
        cursor[i] = ex;
    }
}

__global__ void permute_k(const int* __restrict__ edge, int E,
                          int* __restrict__ cursor, int* __restrict__ perm)
{
    int i = blockIdx.x * blockDim.x + threadIdx.x;
    if (i < E) {
        int s = __ldg(edge + i);
        int d = __ldg(edge + E + i);
        int slot = atomicAdd(&cursor[d], 1);
        perm[slot] = s;
    }
}

// ---------------------------------------------------------------------------
// Gather-side aggregation (mean). One warp per dst row.
// ---------------------------------------------------------------------------
__global__ void __launch_bounds__(256)
agg_k(const float* __restrict__ xsrc,
      const int*   __restrict__ remap,
      const int*   __restrict__ rowptr,
      const int*   __restrict__ perm,
      float* __restrict__ outm,
      int N)
{
    int w = (blockIdx.x * blockDim.x + threadIdx.x) >> 5;
    int lane = threadIdx.x & 31;
    if (w >= N) return;

    int start = __ldg(rowptr + w);
    int end   = __ldg(rowptr + w + 1);

    float ax = 0.0f, ay = 0.0f;
    for (int base = start; base < end; base += 32) {
        int rem = end - base;
        int idx = 0;
        if (lane < rem) {
            idx = __ldg(perm + base + lane);
            if (remap) idx = __ldg(remap + idx);
        }
        int m = rem < 32 ? rem : 32;
        for (int j = 0; j < m; j++) {
            int s2 = __shfl_sync(0xffffffffu, idx, j);
            float2 v = *reinterpret_cast<const float2*>(xsrc + (size_t)s2 * D + lane * 2);
            ax += v.x;
            ay += v.y;
        }
    }

    int deg = end - start;
    float inv = (deg > 0) ? (1.0f / (float)deg) : 0.0f;
    float2 o;
    o.x = ax * inv;
    o.y = ay * inv;
    *reinterpret_cast<float2*>(outm + (size_t)w * D + lane * 2) = o;
}

// ---------------------------------------------------------------------------
// Post GEMM on tensor cores (mma.sync m16n8k16 bf16, 3-pass fp32 emulation).
// B tiles come prepacked from global (no per-block conversion).
// ---------------------------------------------------------------------------
#define PKB 272
#define SM_AHI  0
#define SM_ALO  (128 * PKB)
#define SM_BHI  (2 * 128 * PKB)
#define SM_BLO  (SM_BHI + 64 * PKB)
#define SM_BIAS (SM_BHI + 2 * 64 * PKB)
#define POST_SMEM (SM_BIAS + 256)

#define LDMATRIX_X4(r0, r1, r2, r3, addr) \
    asm volatile("ldmatrix.sync.aligned.m8n8.x4.shared.b16 {%0, %1, %2, %3}, [%4];" \
                 : "=r"(r0), "=r"(r1), "=r"(r2), "=r"(r3) : "r"(addr))

#define MMA_BF16(d, a0, a1, a2, a3, b0, b1) \
    asm volatile("mma.sync.aligned.m16n8k16.row.col.f32.bf16.bf16.f32 " \
                 "{%0, %1, %2, %3}, {%4, %5, %6, %7}, {%8, %9}, {%0, %1, %2, %3};" \
                 : "+f"((d)[0]), "+f"((d)[1]), "+f"((d)[2]), "+f"((d)[3]) \
                 : "r"(a0), "r"(a1), "r"(a2), "r"(a3), "r"(b0), "r"(b1))

__device__ __forceinline__ uint32_t bf2u(__nv_bfloat162 v) {
    return *reinterpret_cast<uint32_t*>(&v);
}

__global__ void __launch_bounds__(256)
sage_post_tc(const float* __restrict__ acc,
             const float* __restrict__ xdst_base,
             const int*   __restrict__ remap,
             const __nv_bfloat16* __restrict__ Bhi,
             const __nv_bfloat16* __restrict__ Blo,
             const float* __restrict__ bl,
             float* __restrict__ out,
             int N, int relu)
{
    extern __shared__ char smem[];
    uint32_t sb = smem_to_u32(smem);
    const int tid = threadIdx.x;
    const int warp = tid >> 5;
    const int lane = tid & 31;
    const int r0 = blockIdx.x * 128;

    // ---- Stage B from prepacked global: vectorized, conflict-free ----
    // 64 rows x 256B = 1024 f4 per plane; 4 f4 per thread per plane.
    #pragma unroll
    for (int pp = 0; pp < 4; pp++) {
        int i = tid + pp * 256;        // f4 idx 0..1023
        int n = i >> 4;                // row 0..63
        int kq = i & 15;               // 16B chunk (8 k)
        *reinterpret_cast<uint4*>(smem + SM_BHI + n * PKB + kq * 16) =
            *reinterpret_cast<const uint4*>(Bhi + n * 128 + kq * 8);
        *reinterpret_cast<uint4*>(smem + SM_BLO + n * PKB + kq * 16) =
            *reinterpret_cast<const uint4*>(Blo + n * 128 + kq * 8);
    }
    if (tid < 64) *reinterpret_cast<float*>(smem + SM_BIAS + tid * 4) = bl[tid];

    // ---- Stage A: row = tid&127, half = tid>>7 (0: agg k0..63, 1: x k64..127)
    {
        int row  = tid & 127;
        int half = tid >> 7;
        int gr   = r0 + row;
        bool ok  = (gr < N);
        const float* p;
        if (half == 0) {
            p = acc + (size_t)(ok ? gr : 0) * D;
        } else {
            int xr = ok ? (remap ? __ldg(remap + gr) : gr) : 0;
            p = xdst_base + (size_t)xr * D;
        }
        char* aHiRow = smem + SM_AHI + row * PKB + half * 128;
        char* aLoRow = smem + SM_ALO + row * PKB + half * 128;
        #pragma unroll
        for (int j = 0; j < 8; j++) {
            float4 v0 = ok ? reinterpret_cast<const float4*>(p)[j * 2]
                           : make_float4(0.f, 0.f, 0.f, 0.f);
            float4 v1 = ok ? reinterpret_cast<const float4*>(p)[j * 2 + 1]
                           : make_float4(0.f, 0.f, 0.f, 0.f);
            __nv_bfloat162 h0 = __float22bfloat162_rn(make_float2(v0.x, v0.y));
            __nv_bfloat162 h1 = __float22bfloat162_rn(make_float2(v0.z, v0.w));
            __nv_bfloat162 h2 = __float22bfloat162_rn(make_float2(v1.x, v1.y));
            __nv_bfloat162 h3 = __float22bfloat162_rn(make_float2(v1.z, v1.w));
            float2 f0 = __bfloat1622float2(h0);
            float2 f1 = __bfloat1622float2(h1);
            float2 f2 = __bfloat1622float2(h2);
            float2 f3 = __bfloat1622float2(h3);
            __nv_bfloat162 l0 = __float22bfloat162_rn(make_float2(v0.x - f0.x, v0.y - f0.y));
            __nv_bfloat162 l1 = __float22bfloat162_rn(make_float2(v0.z - f1.x, v0.w - f1.y));
            __nv_bfloat162 l2 = __float22bfloat162_rn(make_float2(v1.x - f2.x, v1.y - f2.y));
            __nv_bfloat162 l3 = __float22bfloat162_rn(make_float2(v1.z - f3.x, v1.w - f3.y));
            *reinterpret_cast<uint4*>(aHiRow + j * 16) =
                make_uint4(bf2u(h0), bf2u(h1), bf2u(h2), bf2u(h3));
            *reinterpret_cast<uint4*>(aLoRow + j * 16) =
                make_uint4(bf2u(l0), bf2u(l1), bf2u(l2), bf2u(l3));
        }
    }
    __syncthreads();

    // ---- MMA mainloop: 3 passes x 8 k-steps, 8 n-tiles ----
    float d[8][4];
    #pragma unroll
    for (int t = 0; t < 8; t++) {
        d[t][0] = 0.f; d[t][1] = 0.f; d[t][2] = 0.f; d[t][3] = 0.f;
    }

    const uint32_t aRowOff = (uint32_t)(warp * 16 + (lane & 15)) * PKB
                           + (uint32_t)(lane >> 4) * 16;
    const uint32_t bRowOff = (uint32_t)(lane >> 2) * PKB + (uint32_t)(lane & 3) * 4;

    #pragma unroll
    for (int pass = 0; pass < 3; pass++) {
        uint32_t aBase = sb + (pass == 1 ? SM_ALO : SM_AHI) + aRowOff;
        uint32_t bOff  = (pass == 2 ? SM_BLO : SM_BHI) + bRowOff;
        #pragma unroll
        for (int ks = 0; ks < 8; ks++) {
            uint32_t a0, a1, a2, a3;
            LDMATRIX_X4(a0, a1, a2, a3, aBase + ks * 32);
            #pragma unroll
            for (int t = 0; t < 8; t++) {
                uint32_t b0 = *reinterpret_cast<const uint32_t*>(
                    (const char*)smem + bOff + t * 8 * PKB + ks * 32);
                uint32_t b1 = *reinterpret_cast<const uint32_t*>(
                    (const char*)smem + bOff + t * 8 * PKB + ks * 32 + 16);
                MMA_BF16(d[t], a0, a1, a2, a3, b0, b1);
            }
        }
    }

    // ---- Epilogue: bias, row L2 norm (4-lane groups), relu, store ----
    const float* bias = reinterpret_cast<const float*>(smem + SM_BIAS);
    int cBase = (lane & 3) * 2;
    float ssl = 0.f, ssh = 0.f;
    #pragma unroll
    for (int t = 0; t < 8; t++) {
        int c = t * 8 + cBase;
        float b0 = bias[c], b1 = bias[c + 1];
        d[t][0] += b0; d[t][1] += b1;
        d[t][2] += b0; d[t][3] += b1;
        ssl = fmaf(d[t][0], d[t][0], ssl); ssl = fmaf(d[t][1], d[t][1], ssl);
        ssh = fmaf(d[t][2], d[t][2], ssh); ssh = fmaf(d[t][3], d[t][3], ssh);
    }
    ssl += __shfl_xor_sync(0xffffffffu, ssl, 1);
    ssl += __shfl_xor_sync(0xffffffffu, ssl, 2);
    ssh += __shfl_xor_sync(0xffffffffu, ssh, 1);
    ssh += __shfl_xor_sync(0xffffffffu, ssh, 2);

    int rlo = r0 + warp * 16 + (lane >> 2);
    int rhi = rlo + 8;
    float invl = 1.0f / fmaxf(sqrtf(ssl), 1e-12f);
    float invh = 1.0f / fmaxf(sqrtf(ssh), 1e-12f);

    if (rlo < N) {
        float* op = out + (size_t)rlo * D + cBase;
        #pragma unroll
        for (int t = 0; t < 8; t++) {
            float2 v = make_float2(d[t][0] * invl, d[t][1] * invl);
            if (relu) { v.x = fmaxf(v.x, 0.f); v.y = fmaxf(v.y, 0.f); }
            *reinterpret_cast<float2*>(op + t * 8) = v;
        }
    }
    if (rhi < N) {
        float* op = out + (size_t)rhi * D + cBase;
        #pragma unroll
        for (int t = 0; t < 8; t++) {
            float2 v = make_float2(d[t][2] * invh, d[t][3] * invh);
            if (relu) { v.x = fmaxf(v.x, 0.f); v.y = fmaxf(v.y, 0.f); }
            *reinterpret_cast<float2*>(op + t * 8) = v;
        }
    }
}

// ---------------------------------------------------------------------------
// Launch
// ---------------------------------------------------------------------------
extern "C" void kernel_launch(void* const* d_in, const int* in_sizes, int n_in,
                              void* d_out, int out_size)
{
    const float* emb_user = (const float*)d_in[0];
    const float* emb_item = (const float*)d_in[1];
    const float* W1l_ui = (const float*)d_in[2];
    const float* b1_ui  = (const float*)d_in[3];
    const float* W1r_ui = (const float*)d_in[4];
    const float* W1l_iu = (const float*)d_in[5];
    const float* b1_iu  = (const float*)d_in[6];
    const float* W1r_iu = (const float*)d_in[7];
    const float* W2l_ui = (const float*)d_in[8];
    const float* b2_ui  = (const float*)d_in[9];
    const float* W2r_ui = (const float*)d_in[10];
    const float* W2l_iu = (const float*)d_in[11];
    const float* b2_iu  = (const float*)d_in[12];
    const float* W2r_iu = (const float*)d_in[13];
    const int* n_id_user = (const int*)d_in[14];
    const int* n_id_item = (const int*)d_in[15];
    const int* edge_ui   = (const int*)d_in[16];
    const int* edge_iu   = (const int*)d_in[17];

    const int E_ui = in_sizes[16] / 2;
    const int E_iu = in_sizes[17] / 2;

    float* out = (float*)d_out;
    float* out_user = out;
    float* out_item = out + (size_t)NU * D;

    float *acc_i, *acc_u, *h_i, *h_u;
    int *deg_i, *deg_u, *rp_i, *rp_u, *cur_i, *cur_u, *perm_ui, *perm_iu, *bsum, *boff;
    __nv_bfloat16 *Bhi, *Blo;
    cudaGetSymbolAddress((void**)&acc_i, g_acc_i);
    cudaGetSymbolAddress((void**)&acc_u, g_acc_u);
    cudaGetSymbolAddress((void**)&h_i, g_h_i);
    cudaGetSymbolAddress((void**)&h_u, g_h_u);
    cudaGetSymbolAddress((void**)&deg_i, g_deg_i);
    cudaGetSymbolAddress((void**)&deg_u, g_deg_u);
    cudaGetSymbolAddress((void**)&rp_i, g_rp_i);
    cudaGetSymbolAddress((void**)&rp_u, g_rp_u);
    cudaGetSymbolAddress((void**)&cur_i, g_cur_i);
    cudaGetSymbolAddress((void**)&cur_u, g_cur_u);
    cudaGetSymbolAddress((void**)&perm_ui, g_perm_ui);
    cudaGetSymbolAddress((void**)&perm_iu, g_perm_iu);
    cudaGetSymbolAddress((void**)&bsum, g_bsum);
    cudaGetSymbolAddress((void**)&boff, g_boff);
    cudaGetSymbolAddress((void**)&Bhi, g_Bhi);
    cudaGetSymbolAddress((void**)&Blo, g_Blo);

    const int TPB = 256;
    const int eBlocksUI = (E_ui + TPB - 1) / TPB;
    const int eBlocksIU = (E_iu + TPB - 1) / TPB;
    const int aggBlocksI = (NI * 32 + TPB - 1) / TPB;
    const int aggBlocksU = (NU * 32 + TPB - 1) / TPB;
    const int postBlocksI = (NI + 127) / 128;
    const int postBlocksU = (NU + 127) / 128;

    cudaFuncSetAttribute(sage_post_tc,
                         cudaFuncAttributeMaxDynamicSharedMemorySize, POST_SMEM);

    // ---- Weight prepack (once) ----
    prepack_w_k<<<128, 256>>>(W1l_ui, W1r_ui, W1l_iu, W1r_iu,
                              W2l_ui, W2r_ui, W2l_iu, W2r_iu);

    // ---- CSR build ----
    cudaMemsetAsync(deg_i, 0, NI * sizeof(int));
    cudaMemsetAsync(deg_u, 0, NU * sizeof(int));

    hist_k<<<eBlocksUI, TPB>>>(edge_ui + E_ui, E_ui, deg_i);
    hist_k<<<eBlocksIU, TPB>>>(edge_iu + E_iu, E_iu, deg_u);

    scanA_k<<<NB_I, 256>>>(deg_i, NI, bsum);
    scanB_k<<<1, 1024>>>(bsum, NB_I, boff, rp_i, NI);
    scanC_k<<<NB_I, 256>>>(deg_i, NI, boff, rp_i, cur_i);
    permute_k<<<eBlocksUI, TPB>>>(edge_ui, E_ui, cur_i, perm_ui);

    scanA_k<<<NB_U, 256>>>(deg_u, NU, bsum);
    scanB_k<<<1, 1024>>>(bsum, NB_U, boff, rp_u, NU);
    scanC_k<<<NB_U, 256>>>(deg_u, NU, boff, rp_u, cur_u);
    permute_k<<<eBlocksIU, TPB>>>(edge_iu, E_iu, cur_u, perm_iu);

    // ---- Layer 1 ----
    agg_k<<<aggBlocksI, TPB>>>(emb_user, n_id_user, rp_i, perm_ui, acc_i, NI);
    agg_k<<<aggBlocksU, TPB>>>(emb_item, n_id_item, rp_u, perm_iu, acc_u, NU);

    sage_post_tc<<<postBlocksI, TPB, POST_SMEM>>>(acc_i, emb_item, n_id_item,
                                                  Bhi + 0 * 8192, Blo + 0 * 8192,
                                                  b1_ui, h_i, NI, 1);
    sage_post_tc<<<postBlocksU, TPB, POST_SMEM>>>(acc_u, emb_user, n_id_user,
                                                  Bhi + 1 * 8192, Blo + 1 * 8192,
                                                  b1_iu, h_u, NU, 1);

    // ---- Layer 2 (same CSR) ----
    agg_k<<<aggBlocksI, TPB>>>(h_u, nullptr, rp_i, perm_ui, acc_i, NI);
    agg_k<<<aggBlocksU, TPB>>>(h_i, nullptr, rp_u, perm_iu, acc_u, NU);

    sage_post_tc<<<postBlocksI, TPB, POST_SMEM>>>(acc_i, h_i, nullptr,
                                                  Bhi + 2 * 8192, Blo + 2 * 8192,
                                                  b2_ui, out_item, NI, 0);
    sage_post_tc<<<postBlocksU, TPB, POST_SMEM>>>(acc_u, h_u, nullptr,
                                                  Bhi + 3 * 8192, Blo + 3 * 8192,
                                                  b2_iu, out_user, NU, 0);
}